// round 16
// baseline (speedup 1.0000x reference)
#include <cuda_runtime.h>
#include <cstdint>

#define NN   100000
#define D    128
#define NOUT 40
#define EMAX 640000
#define SCAN_B 512
#define NB ((NN + SCAN_B - 1) / SCAN_B)   // 196
#define NP64 ((size_t)(NN + 128) * 64)    // plane size w/ tail padding

// ---------------- scratch (device globals: allocation-free) ----------------
__device__ int      g_cnti[NN];
__device__ int      g_incl[NN];
__device__ int      g_bsums[256];
__device__ int      g_rowend[NN];
__device__ int      g_fill[NN];
__device__ int      g_csrc[EMAX];
__device__ uint32_t g_xhi[NP64], g_xlo[NP64];
__device__ uint32_t g_ahi[NP64], g_alo[NP64];
__device__ uint32_t g_p1hi[NP64], g_p1lo[NP64];
__device__ uint32_t g_p2hi[NP64], g_p2lo[NP64];
__device__ float    g_hC[(size_t)NN * D];   // h fallback
// weight planes [n][kp]; 0=W1l 1=W1r 2=W2l 3=W2r 4=W3l 5=W3r 6=Wf1 7=Wf2pad
__device__ uint32_t g_whi[8][128 * 64];
__device__ uint32_t g_wlo[8][128 * 64];
__device__ float    g_bf2p[128];

// ---------------- helpers ----------------
__device__ __forceinline__ uint32_t pack_bf16(float x0, float x1) {
    uint32_t r;
    asm("cvt.rn.bf16x2.f32 %0, %1, %2;" : "=r"(r) : "f"(x1), "f"(x0));
    return r;
}
__device__ __forceinline__ float blo(uint32_t u) { return __uint_as_float(u << 16); }
__device__ __forceinline__ float bhi(uint32_t u) { return __uint_as_float(u & 0xFFFF0000u); }
__device__ __forceinline__ uint32_t smem_u32(const void* p) {
    uint32_t a;
    asm("{ .reg .u64 t; cvta.to.shared.u64 t, %1; cvt.u32.u64 %0, t; }" : "=r"(a) : "l"(p));
    return a;
}
__device__ __forceinline__ void cpa16(uint32_t dst, const void* src) {
    asm volatile("cp.async.cg.shared.global [%0], [%1], 16;" :: "r"(dst), "l"(src));
}
#define CPA_COMMIT() asm volatile("cp.async.commit_group;" ::: "memory")
#define CPA_WAIT1()  asm volatile("cp.async.wait_group 1;" ::: "memory")
#define CPA_WAIT0()  asm volatile("cp.async.wait_group 0;" ::: "memory")

#define MMA_BF16(d, a, b)                                                     \
    asm volatile(                                                             \
        "mma.sync.aligned.m16n8k16.row.col.f32.bf16.bf16.f32 "                \
        "{%0,%1,%2,%3}, {%4,%5,%6,%7}, {%8,%9}, {%0,%1,%2,%3};"               \
        : "+f"(d[0]), "+f"(d[1]), "+f"(d[2]), "+f"(d[3])                      \
        : "r"(a[0]), "r"(a[1]), "r"(a[2]), "r"(a[3]), "r"(b[0]), "r"(b[1]))

#define LDSM4(r, addr)                                                        \
    asm volatile("ldmatrix.sync.aligned.m8n8.x4.shared.b16 {%0,%1,%2,%3}, [%4];" \
        : "=r"((r)[0]), "=r"((r)[1]), "=r"((r)[2]), "=r"((r)[3]) : "r"(addr))

// ---------------- CSR build ----------------
__global__ void k_hist(const int* __restrict__ dst, int E) {
    int e = blockIdx.x * blockDim.x + threadIdx.x;
    if (e < E) atomicAdd(&g_cnti[dst[e]], 1);
}
__global__ void k_scan1(int n) {
    __shared__ int sh[SCAN_B];
    int i = blockIdx.x * SCAN_B + threadIdx.x;
    int v = (i < n) ? g_cnti[i] : 0;
    sh[threadIdx.x] = v;
    __syncthreads();
    for (int off = 1; off < SCAN_B; off <<= 1) {
        int t = (threadIdx.x >= off) ? sh[threadIdx.x - off] : 0;
        __syncthreads();
        sh[threadIdx.x] += t;
        __syncthreads();
    }
    if (i < n) g_incl[i] = sh[threadIdx.x];
    if (threadIdx.x == SCAN_B - 1) g_bsums[blockIdx.x] = sh[SCAN_B - 1];
}
__global__ void k_scan3(int n) {
    __shared__ int sb2[256];
    int t = threadIdx.x;
    if (t < 256) sb2[t] = (t < NB) ? g_bsums[t] : 0;
    __syncthreads();
    for (int off = 1; off < 256; off <<= 1) {
        int x = (t >= off && t < 256) ? sb2[t - off] : 0;
        __syncthreads();
        if (t < 256) sb2[t] += x;
        __syncthreads();
    }
    int add = blockIdx.x ? sb2[blockIdx.x - 1] : 0;
    int i = blockIdx.x * SCAN_B + t;
    if (i >= n) return;
    int e = g_incl[i] + add;
    g_rowend[i] = e;
    g_fill[i] = e - g_cnti[i];
    g_cnti[i] = 0;
}
__global__ void k_fill(const int* __restrict__ src, const int* __restrict__ dst, int E) {
    int e = blockIdx.x * blockDim.x + threadIdx.x;
    if (e >= E) return;
    int p = atomicAdd(&g_fill[dst[e]], 1);
    g_csrc[p] = src[e];
}

// ---------------- merged prep: weights + bias pad + x split + degree hist ---
struct WPtrs { const float* w[8]; };
__global__ void k_prep(WPtrs wp, const float* __restrict__ bf2,
                       const float* __restrict__ x,
                       const int* __restrict__ dst, int E) {
    int i = blockIdx.x * blockDim.x + threadIdx.x;
    if (i < 8 * 8192) {
        int w = i >> 13;
        int r = i & 8191;
        int kp = r >> 7, n = r & 127;
        const float* W = wp.w[w];
        float f0, f1;
        if (w == 7) {
            f0 = (n < NOUT) ? W[(2 * kp) * NOUT + n] : 0.f;
            f1 = (n < NOUT) ? W[(2 * kp + 1) * NOUT + n] : 0.f;
        } else {
            f0 = W[(2 * kp) * 128 + n];
            f1 = W[(2 * kp + 1) * 128 + n];
        }
        uint32_t hi = pack_bf16(f0, f1);
        uint32_t lo = pack_bf16(f0 - blo(hi), f1 - bhi(hi));
        g_whi[w][n * 64 + kp] = hi;
        g_wlo[w][n * 64 + kp] = lo;
    }
    if (i < 128) g_bf2p[i] = (i < NOUT) ? bf2[i] : 0.f;
    if (i < NN * 64) {
        int row = i >> 6, kp = i & 63;
        float2 f = *(const float2*)(x + (size_t)row * D + kp * 2);
        uint32_t hi = pack_bf16(f.x, f.y);
        uint32_t lo = pack_bf16(f.x - blo(hi), f.y - bhi(hi));
        g_xhi[i] = hi;
        g_xlo[i] = lo;
    }
    if (i < E) atomicAdd(&g_cnti[dst[i]], 1);
}

// ---------------- gather mean aggregation on planes (4-edge ILP) ------------
__global__ void k_agg_p(const uint32_t* __restrict__ Ihi, const uint32_t* __restrict__ Ilo,
                        uint32_t* __restrict__ Ohi, uint32_t* __restrict__ Olo) {
    int w = (blockIdx.x * blockDim.x + threadIdx.x) >> 5;
    if (w >= NN) return;
    int lane = threadIdx.x & 31;
    int end = g_rowend[w];
    int start = w ? g_rowend[w - 1] : 0;
    float a0 = 0.f, a1 = 0.f, a2 = 0.f, a3 = 0.f;
    float b0 = 0.f, b1 = 0.f, b2 = 0.f, b3 = 0.f;
    int j = start;
    for (; j + 4 <= end; j += 4) {
        int s0 = g_csrc[j], s1 = g_csrc[j + 1], s2 = g_csrc[j + 2], s3 = g_csrc[j + 3];
        uint2 h0 = *(const uint2*)&Ihi[(size_t)s0 * 64 + lane * 2];
        uint2 l0 = *(const uint2*)&Ilo[(size_t)s0 * 64 + lane * 2];
        uint2 h1 = *(const uint2*)&Ihi[(size_t)s1 * 64 + lane * 2];
        uint2 l1 = *(const uint2*)&Ilo[(size_t)s1 * 64 + lane * 2];
        uint2 h2 = *(const uint2*)&Ihi[(size_t)s2 * 64 + lane * 2];
        uint2 l2 = *(const uint2*)&Ilo[(size_t)s2 * 64 + lane * 2];
        uint2 h3 = *(const uint2*)&Ihi[(size_t)s3 * 64 + lane * 2];
        uint2 l3 = *(const uint2*)&Ilo[(size_t)s3 * 64 + lane * 2];
        a0 += blo(h0.x) + blo(l0.x);  a1 += bhi(h0.x) + bhi(l0.x);
        a2 += blo(h0.y) + blo(l0.y);  a3 += bhi(h0.y) + bhi(l0.y);
        b0 += blo(h1.x) + blo(l1.x);  b1 += bhi(h1.x) + bhi(l1.x);
        b2 += blo(h1.y) + blo(l1.y);  b3 += bhi(h1.y) + bhi(l1.y);
        a0 += blo(h2.x) + blo(l2.x);  a1 += bhi(h2.x) + bhi(l2.x);
        a2 += blo(h2.y) + blo(l2.y);  a3 += bhi(h2.y) + bhi(l2.y);
        b0 += blo(h3.x) + blo(l3.x);  b1 += bhi(h3.x) + bhi(l3.x);
        b2 += blo(h3.y) + blo(l3.y);  b3 += bhi(h3.y) + bhi(l3.y);
    }
    for (; j < end; j++) {
        int s = g_csrc[j];
        uint2 h = *(const uint2*)&Ihi[(size_t)s * 64 + lane * 2];
        uint2 l = *(const uint2*)&Ilo[(size_t)s * 64 + lane * 2];
        a0 += blo(h.x) + blo(l.x);  a1 += bhi(h.x) + bhi(l.x);
        a2 += blo(h.y) + blo(l.y);  a3 += bhi(h.y) + bhi(l.y);
    }
    a0 += b0; a1 += b1; a2 += b2; a3 += b3;
    int deg = end - start;
    float sc = deg > 0 ? 1.0f / (float)deg : 0.f;
    a0 *= sc; a1 *= sc; a2 *= sc; a3 *= sc;
    uint32_t h0 = pack_bf16(a0, a1);
    uint32_t l0 = pack_bf16(a0 - blo(h0), a1 - bhi(h0));
    uint32_t h1 = pack_bf16(a2, a3);
    uint32_t l1 = pack_bf16(a2 - blo(h1), a3 - bhi(h1));
    *(uint2*)&Ohi[(size_t)w * 64 + lane * 2] = make_uint2(h0, h1);
    *(uint2*)&Olo[(size_t)w * 64 + lane * 2] = make_uint2(l0, l1);
}

// ---------------- async double-buffered bf16 3-pass GEMM (ldmatrix) --------
// epilogue: smem-staged, coalesced STG.128
#define PST    20
#define PLSZ   2560
#define STSZ   (4 * PLSZ)
#define SMEMB  (2 * STSZ * 4)
#define EST    68                  // epilogue smem stride (conflict-free STS)
// OUTMODE: 0 = planes, 1 = planes + f32
template <bool DUAL, bool RELU, int OUTMODE>
__global__ __launch_bounds__(256, 2) void k_mma_p(
    const uint32_t* __restrict__ ALhi, const uint32_t* __restrict__ ALlo,
    const uint32_t* __restrict__ ARhi, const uint32_t* __restrict__ ARlo,
    const uint32_t* __restrict__ BhiL, const uint32_t* __restrict__ BloL,
    const uint32_t* __restrict__ BhiR, const uint32_t* __restrict__ BloR,
    const float* __restrict__ bias,
    uint32_t* __restrict__ OHi, uint32_t* __restrict__ OLo,
    float* __restrict__ Of32, int nrows)
{
    extern __shared__ uint32_t sm[];
    const uint32_t sb = smem_u32(sm);
    const int tid = threadIdx.x;
    const int wid = tid >> 5, lane = tid & 31;
    const int wr = wid >> 1, wc = wid & 1;
    const int row0 = blockIdx.x * 128;
    const int warp_m = wr * 32;
    const int warp_n = wc * 64;
    const int lq = lane >> 2;
    const int lr = lane & 3;
    const int NCH = DUAL ? 8 : 4;

    const uint32_t aRow = (uint32_t)(warp_m + (lane & 15)) * PST + ((lane & 16) >> 2);
    const uint32_t bRow = (uint32_t)(warp_n + (lane & 7) + ((lane & 16) >> 1)) * PST
                        + ((lane & 8) >> 3) * 4;

    auto issue = [&](int ch) {
        const bool right = DUAL && (ch >= 4);
        const uint32_t* Ah = right ? ARhi : ALhi;
        const uint32_t* Al = right ? ARlo : ALlo;
        const uint32_t* Bh = right ? BhiR : BhiL;
        const uint32_t* Bl = right ? BloR : BloL;
        const int kpb = (ch & 3) * 16;
        const uint32_t base = sb + (uint32_t)(ch & 1) * STSZ * 4;
#pragma unroll
        for (int c = tid; c < 512; c += 256) {
            int r = c >> 2, kg = (c & 3) * 4;
            uint32_t doff = (uint32_t)(r * PST + kg) * 4;
            size_t asrc = (size_t)(row0 + r) * 64 + kpb + kg;
            size_t bsrc = (size_t)r * 64 + kpb + kg;
            cpa16(base + doff,                Ah + asrc);
            cpa16(base + PLSZ * 4 + doff,     Al + asrc);
            cpa16(base + 2 * PLSZ * 4 + doff, Bh + bsrc);
            cpa16(base + 3 * PLSZ * 4 + doff, Bl + bsrc);
        }
        CPA_COMMIT();
    };

    float acc[2][8][4];
#pragma unroll
    for (int m = 0; m < 2; m++)
#pragma unroll
        for (int n = 0; n < 8; n++)
#pragma unroll
            for (int i = 0; i < 4; i++) acc[m][n][i] = 0.f;

    issue(0);
    for (int ch = 0; ch < NCH; ch++) {
        CPA_WAIT0();
        __syncthreads();
        if (ch + 1 < NCH) issue(ch + 1);

        const uint32_t stA = sb + (uint32_t)(ch & 1) * STSZ * 4;

#pragma unroll
        for (int kbu = 0; kbu < 16; kbu += 8) {
            uint32_t ahi[2][4], alo[2][4];
#pragma unroll
            for (int m = 0; m < 2; m++) {
                uint32_t ao = (aRow + (uint32_t)m * 16 * PST + kbu) * 4;
                LDSM4(ahi[m], stA + ao);
                LDSM4(alo[m], stA + PLSZ * 4 + ao);
            }
            uint32_t bh[4][4], bl[4][4];
#pragma unroll
            for (int p = 0; p < 4; p++) {
                uint32_t bo = (bRow + (uint32_t)p * 16 * PST + kbu) * 4;
                LDSM4(bh[p], stA + 2 * PLSZ * 4 + bo);
                LDSM4(bl[p], stA + 3 * PLSZ * 4 + bo);
            }
#pragma unroll
            for (int p = 0; p < 4; p++) {
#pragma unroll
                for (int m = 0; m < 2; m++) {
                    MMA_BF16(acc[m][2 * p],     ahi[m], bh[p]);
                    MMA_BF16(acc[m][2 * p],     alo[m], bh[p]);
                    MMA_BF16(acc[m][2 * p],     ahi[m], bl[p]);
                    MMA_BF16(acc[m][2 * p + 1], ahi[m], (bh[p] + 2));
                    MMA_BF16(acc[m][2 * p + 1], alo[m], (bh[p] + 2));
                    MMA_BF16(acc[m][2 * p + 1], ahi[m], (bl[p] + 2));
                }
            }
        }
    }

    // ---- staged epilogue: smem [row][kp] stride EST, then coalesced STG.128
    __syncthreads();   // done with pipeline stages; reuse smem
    uint32_t* eh = sm;                 // hi plane 128 x EST
    uint32_t* el = sm + 128 * EST;     // lo plane
#pragma unroll
    for (int m = 0; m < 2; m++) {
#pragma unroll
        for (int half = 0; half < 2; half++) {
            int rl = warp_m + m * 16 + lq + half * 8;
            int grow = row0 + rl;
#pragma unroll
            for (int n = 0; n < 8; n++) {
                int c = warp_n + n * 8 + lr * 2;
                float v0 = acc[m][n][half * 2 + 0] + bias[c];
                float v1 = acc[m][n][half * 2 + 1] + bias[c + 1];
                if (RELU) { v0 = fmaxf(v0, 0.f); v1 = fmaxf(v1, 0.f); }
                uint32_t hi = pack_bf16(v0, v1);
                uint32_t lo = pack_bf16(v0 - blo(hi), v1 - bhi(hi));
                int kp = c >> 1;
                eh[rl * EST + kp] = hi;
                el[rl * EST + kp] = lo;
                if (OUTMODE == 1 && grow < nrows)
                    *(float2*)(Of32 + (size_t)grow * D + c) = make_float2(v0, v1);
            }
        }
    }
    __syncthreads();
    {
        int r = tid >> 1, ko = (tid & 1) * 32;
        int grow = row0 + r;
        if (grow < nrows) {
            const uint32_t* sh = eh + r * EST + ko;
            const uint32_t* sl = el + r * EST + ko;
            uint32_t* gh = OHi + (size_t)grow * 64 + ko;
            uint32_t* gl = OLo + (size_t)grow * 64 + ko;
#pragma unroll
            for (int i = 0; i < 8; i++)
                *(uint4*)(gh + i * 4) = *(const uint4*)(sh + i * 4);
#pragma unroll
            for (int i = 0; i < 8; i++)
                *(uint4*)(gl + i * 4) = *(const uint4*)(sl + i * 4);
        }
    }
}

// ---------------- fused fc2 (N=64 padded) + log_softmax (ldmatrix) ---------
#define BST 20
#define FA_PLSZ (128 * PST)
#define FA_ST   (2 * FA_PLSZ)
#define FB_PL   (64 * BST)
#define FB_OFF  (2 * FA_ST)
#define F2SMEM  ((FB_OFF + 8 * FB_PL) * 4)
__global__ __launch_bounds__(256, 2) void k_fc2lsm(
    const uint32_t* __restrict__ Ahi_g, const uint32_t* __restrict__ Alo_g,
    const uint32_t* __restrict__ Bh_g, const uint32_t* __restrict__ Bl_g,
    const float* __restrict__ bias, float* __restrict__ out, int nrows)
{
    extern __shared__ uint32_t sm[];
    const uint32_t sb = smem_u32(sm);
    const int tid = threadIdx.x;
    const int wid = tid >> 5, lane = tid & 31;
    const int row0 = blockIdx.x * 128;
    const int lq = lane >> 2;
    const int lr = lane & 3;

    const uint32_t aRow = (uint32_t)(wid * 16 + (lane & 15)) * PST + ((lane & 16) >> 2);
    const uint32_t bRow = (uint32_t)((lane & 7) + ((lane & 16) >> 1)) * BST
                        + ((lane & 8) >> 3) * 4;

    {
        int c = tid;
        int col = c >> 2, kg = (c & 3) * 4;
#pragma unroll
        for (int ch = 0; ch < 4; ch++) {
            size_t src = (size_t)col * 64 + ch * 16 + kg;
            uint32_t doff = (uint32_t)(col * BST + kg) * 4;
            cpa16(sb + (FB_OFF + (2 * ch) * FB_PL) * 4 + doff,     Bh_g + src);
            cpa16(sb + (FB_OFF + (2 * ch + 1) * FB_PL) * 4 + doff, Bl_g + src);
        }
    }
    CPA_COMMIT();

    auto issueA = [&](int ch) {
        const uint32_t base = sb + (uint32_t)(ch & 1) * FA_ST * 4;
        const int kpb = ch * 16;
#pragma unroll
        for (int c = tid; c < 512; c += 256) {
            int r = c >> 2, kg = (c & 3) * 4;
            uint32_t doff = (uint32_t)(r * PST + kg) * 4;
            size_t src = (size_t)(row0 + r) * 64 + kpb + kg;
            cpa16(base + doff,               Ahi_g + src);
            cpa16(base + FA_PLSZ * 4 + doff, Alo_g + src);
        }
        CPA_COMMIT();
    };

    float acc[8][4];
#pragma unroll
    for (int n = 0; n < 8; n++)
#pragma unroll
        for (int i = 0; i < 4; i++) acc[n][i] = 0.f;

    issueA(0);
    for (int ch = 0; ch < 4; ch++) {
        if (ch + 1 < 4) { issueA(ch + 1); CPA_WAIT1(); }
        else            { CPA_WAIT0(); }
        __syncthreads();

        const uint32_t stA = sb + (uint32_t)(ch & 1) * FA_ST * 4;
        const uint32_t stB = sb + (uint32_t)(FB_OFF + (2 * ch) * FB_PL) * 4;

#pragma unroll
        for (int kbu = 0; kbu < 16; kbu += 8) {
            uint32_t ahi[4], alo[4];
            uint32_t ao = (aRow + kbu) * 4;
            LDSM4(ahi, stA + ao);
            LDSM4(alo, stA + FA_PLSZ * 4 + ao);
            uint32_t bh[4][4], bl[4][4];
#pragma unroll
            for (int p = 0; p < 4; p++) {
                uint32_t bo = (bRow + (uint32_t)p * 16 * BST + kbu) * 4;
                LDSM4(bh[p], stB + bo);
                LDSM4(bl[p], stB + FB_PL * 4 + bo);
            }
#pragma unroll
            for (int p = 0; p < 4; p++) {
                MMA_BF16(acc[2 * p],     ahi, bh[p]);
                MMA_BF16(acc[2 * p],     alo, bh[p]);
                MMA_BF16(acc[2 * p],     ahi, bl[p]);
                MMA_BF16(acc[2 * p + 1], ahi, (bh[p] + 2));
                MMA_BF16(acc[2 * p + 1], alo, (bh[p] + 2));
                MMA_BF16(acc[2 * p + 1], ahi, (bl[p] + 2));
            }
        }
        __syncthreads();
    }

#pragma unroll
    for (int half = 0; half < 2; half++) {
        int row = row0 + wid * 16 + lq + half * 8;
        float z[5][2];
        float mx = -1e30f;
#pragma unroll
        for (int n = 0; n < 5; n++) {
            int c = n * 8 + lr * 2;
            z[n][0] = acc[n][half * 2 + 0] + bias[c];
            z[n][1] = acc[n][half * 2 + 1] + bias[c + 1];
            mx = fmaxf(mx, fmaxf(z[n][0], z[n][1]));
        }
        mx = fmaxf(mx, __shfl_xor_sync(0xffffffffu, mx, 1));
        mx = fmaxf(mx, __shfl_xor_sync(0xffffffffu, mx, 2));
        float s = 0.f;
#pragma unroll
        for (int n = 0; n < 5; n++)
            s += expf(z[n][0] - mx) + expf(z[n][1] - mx);
        s += __shfl_xor_sync(0xffffffffu, s, 1);
        s += __shfl_xor_sync(0xffffffffu, s, 2);
        float l = mx + logf(s);
        if (row < nrows) {
#pragma unroll
            for (int n = 0; n < 5; n++) {
                int c = n * 8 + lr * 2;
                *(float2*)(out + (size_t)row * NOUT + c) =
                    make_float2(z[n][0] - l, z[n][1] - l);
            }
        }
    }
}

// ---------------- launch ----------------
extern "C" void kernel_launch(void* const* d_in, const int* in_sizes, int n_in,
                              void* d_out, int out_size) {
    const float* x    = (const float*)d_in[0];
    const int* ei     = (const int*)d_in[1];   // int32 (JAX x64-disabled)
    const int E = in_sizes[1] / 2;
    const int* src = ei;
    const int* dst = ei + E;
    const float* W1l = (const float*)d_in[2];
    const float* b1  = (const float*)d_in[3];
    const float* W1r = (const float*)d_in[4];
    const float* W2l = (const float*)d_in[5];
    const float* b2  = (const float*)d_in[6];
    const float* W2r = (const float*)d_in[7];
    const float* W3l = (const float*)d_in[8];
    const float* b3  = (const float*)d_in[9];
    const float* W3r = (const float*)d_in[10];
    const float* Wf1 = (const float*)d_in[11];
    const float* bf1 = (const float*)d_in[12];
    const float* Wf2 = (const float*)d_in[13];
    const float* bf2 = (const float*)d_in[14];

    float* out = (float*)d_out;

    uint32_t *xhi, *xlo, *ahi, *alo, *p1hi, *p1lo, *p2hi, *p2lo, *whi, *wlo;
    float *hC, *bf2p;
    cudaGetSymbolAddress((void**)&xhi, g_xhi);
    cudaGetSymbolAddress((void**)&xlo, g_xlo);
    cudaGetSymbolAddress((void**)&ahi, g_ahi);
    cudaGetSymbolAddress((void**)&alo, g_alo);
    cudaGetSymbolAddress((void**)&p1hi, g_p1hi);
    cudaGetSymbolAddress((void**)&p1lo, g_p1lo);
    cudaGetSymbolAddress((void**)&p2hi, g_p2hi);
    cudaGetSymbolAddress((void**)&p2lo, g_p2lo);
    cudaGetSymbolAddress((void**)&whi, g_whi);
    cudaGetSymbolAddress((void**)&wlo, g_wlo);
    cudaGetSymbolAddress((void**)&hC, g_hC);
    cudaGetSymbolAddress((void**)&bf2p, g_bf2p);

    float* h_out = (out_size >= NN * (NOUT + D)) ? (out + (size_t)NN * NOUT) : hC;

    cudaFuncSetAttribute(k_mma_p<true, true, 0>,  cudaFuncAttributeMaxDynamicSharedMemorySize, SMEMB);
    cudaFuncSetAttribute(k_mma_p<true, false, 1>, cudaFuncAttributeMaxDynamicSharedMemorySize, SMEMB);
    cudaFuncSetAttribute(k_mma_p<false, true, 0>, cudaFuncAttributeMaxDynamicSharedMemorySize, SMEMB);
    cudaFuncSetAttribute(k_fc2lsm, cudaFuncAttributeMaxDynamicSharedMemorySize, F2SMEM);

    const int T = 256;
    const int gE    = (E + T - 1) / T;
    const int gAggW = (int)(((size_t)NN * 32 + T - 1) / T);
    const int gGemm = (NN + 127) / 128;

    WPtrs wp;
    wp.w[0] = W1l; wp.w[1] = W1r; wp.w[2] = W2l; wp.w[3] = W2r;
    wp.w[4] = W3l; wp.w[5] = W3r; wp.w[6] = Wf1; wp.w[7] = Wf2;

#define WH(i) (whi + (size_t)(i) * 8192)
#define WL(i) (wlo + (size_t)(i) * 8192)

    k_prep<<<(NN * 64 + T - 1) / T, T>>>(wp, bf2, x, dst, E);
    k_scan1<<<NB, SCAN_B>>>(NN);
    k_scan3<<<NB, SCAN_B>>>(NN);
    k_fill<<<gE, T>>>(src, dst, E);

    // layer 1
    k_agg_p<<<gAggW, T>>>(xhi, xlo, ahi, alo);
    k_mma_p<true, true, 0><<<gGemm, T, SMEMB>>>(ahi, alo, xhi, xlo,
        WH(0), WL(0), WH(1), WL(1), b1, p1hi, p1lo, nullptr, NN);
    // layer 2
    k_agg_p<<<gAggW, T>>>(p1hi, p1lo, ahi, alo);
    k_mma_p<true, true, 0><<<gGemm, T, SMEMB>>>(ahi, alo, p1hi, p1lo,
        WH(2), WL(2), WH(3), WL(3), b2, p2hi, p2lo, nullptr, NN);
    // layer 3 (no relu): planes + exact f32 h
    k_agg_p<<<gAggW, T>>>(p2hi, p2lo, ahi, alo);
    k_mma_p<true, false, 1><<<gGemm, T, SMEMB>>>(ahi, alo, p2hi, p2lo,
        WH(4), WL(4), WH(5), WL(5), b3, p1hi, p1lo, h_out, NN);
    // fc1 (relu) -> p2 planes
    k_mma_p<false, true, 0><<<gGemm, T, SMEMB>>>(p1hi, p1lo, nullptr, nullptr,
        WH(6), WL(6), nullptr, nullptr, bf1, p2hi, p2lo, nullptr, NN);
    // fc2 + log_softmax fused
    k_fc2lsm<<<gGemm, T, F2SMEM>>>(p2hi, p2lo, WH(7), WL(7), bf2p, out, NN);
}

// round 17
// speedup vs baseline: 1.0595x; 1.0595x over previous
#include <cuda_runtime.h>
#include <cstdint>

#define NN   100000
#define D    128
#define NOUT 40
#define EMAX 640000
#define SCAN_B 512
#define NB ((NN + SCAN_B - 1) / SCAN_B)   // 196
#define NP64 ((size_t)(NN + 128) * 64)    // plane size w/ tail padding

// ---------------- scratch (device globals: allocation-free) ----------------
__device__ int      g_cnti[NN];
__device__ int      g_incl[NN];
__device__ int      g_bsums[256];
__device__ int      g_rowend[NN];
__device__ int      g_fill[NN];
__device__ int      g_csrc[EMAX];
__device__ uint32_t g_xhi[NP64], g_xlo[NP64];
__device__ uint32_t g_ahi[NP64], g_alo[NP64];
__device__ uint32_t g_p1hi[NP64], g_p1lo[NP64];
__device__ uint32_t g_p2hi[NP64], g_p2lo[NP64];
__device__ float    g_hC[(size_t)NN * D];   // h fallback
// weight planes [n][kp]; 0=W1l 1=W1r 2=W2l 3=W2r 4=W3l 5=W3r 6=Wf1 7=Wf2pad
__device__ uint32_t g_whi[8][128 * 64];
__device__ uint32_t g_wlo[8][128 * 64];
__device__ float    g_bf2p[128];

// ---------------- helpers ----------------
__device__ __forceinline__ uint32_t pack_bf16(float x0, float x1) {
    uint32_t r;
    asm("cvt.rn.bf16x2.f32 %0, %1, %2;" : "=r"(r) : "f"(x1), "f"(x0));
    return r;
}
__device__ __forceinline__ float blo(uint32_t u) { return __uint_as_float(u << 16); }
__device__ __forceinline__ float bhi(uint32_t u) { return __uint_as_float(u & 0xFFFF0000u); }
__device__ __forceinline__ uint32_t smem_u32(const void* p) {
    uint32_t a;
    asm("{ .reg .u64 t; cvta.to.shared.u64 t, %1; cvt.u32.u64 %0, t; }" : "=r"(a) : "l"(p));
    return a;
}
__device__ __forceinline__ void cpa16(uint32_t dst, const void* src) {
    asm volatile("cp.async.cg.shared.global [%0], [%1], 16;" :: "r"(dst), "l"(src));
}
#define CPA_COMMIT() asm volatile("cp.async.commit_group;" ::: "memory")
#define CPA_WAIT1()  asm volatile("cp.async.wait_group 1;" ::: "memory")
#define CPA_WAIT0()  asm volatile("cp.async.wait_group 0;" ::: "memory")

#define MMA_BF16(d, a, b)                                                     \
    asm volatile(                                                             \
        "mma.sync.aligned.m16n8k16.row.col.f32.bf16.bf16.f32 "                \
        "{%0,%1,%2,%3}, {%4,%5,%6,%7}, {%8,%9}, {%0,%1,%2,%3};"               \
        : "+f"(d[0]), "+f"(d[1]), "+f"(d[2]), "+f"(d[3])                      \
        : "r"(a[0]), "r"(a[1]), "r"(a[2]), "r"(a[3]), "r"(b[0]), "r"(b[1]))

#define LDSM4(r, addr)                                                        \
    asm volatile("ldmatrix.sync.aligned.m8n8.x4.shared.b16 {%0,%1,%2,%3}, [%4];" \
        : "=r"((r)[0]), "=r"((r)[1]), "=r"((r)[2]), "=r"((r)[3]) : "r"(addr))

// ---------------- CSR build ----------------
__global__ void k_scan1(int n) {
    __shared__ int sh[SCAN_B];
    int i = blockIdx.x * SCAN_B + threadIdx.x;
    int v = (i < n) ? g_cnti[i] : 0;
    sh[threadIdx.x] = v;
    __syncthreads();
    for (int off = 1; off < SCAN_B; off <<= 1) {
        int t = (threadIdx.x >= off) ? sh[threadIdx.x - off] : 0;
        __syncthreads();
        sh[threadIdx.x] += t;
        __syncthreads();
    }
    if (i < n) g_incl[i] = sh[threadIdx.x];
    if (threadIdx.x == SCAN_B - 1) g_bsums[blockIdx.x] = sh[SCAN_B - 1];
}
__global__ void k_scan3(int n) {
    __shared__ int sb2[256];
    int t = threadIdx.x;
    if (t < 256) sb2[t] = (t < NB) ? g_bsums[t] : 0;
    __syncthreads();
    for (int off = 1; off < 256; off <<= 1) {
        int x = (t >= off && t < 256) ? sb2[t - off] : 0;
        __syncthreads();
        if (t < 256) sb2[t] += x;
        __syncthreads();
    }
    int add = blockIdx.x ? sb2[blockIdx.x - 1] : 0;
    int i = blockIdx.x * SCAN_B + t;
    if (i >= n) return;
    int e = g_incl[i] + add;
    g_rowend[i] = e;
    g_fill[i] = e - g_cnti[i];
    g_cnti[i] = 0;
}
__global__ void k_fill(const int* __restrict__ src, const int* __restrict__ dst, int E) {
    int e = blockIdx.x * blockDim.x + threadIdx.x;
    if (e >= E) return;
    int p = atomicAdd(&g_fill[dst[e]], 1);
    g_csrc[p] = src[e];
}

// ---------------- merged prep: weights + bias pad + x split + degree hist ---
struct WPtrs { const float* w[8]; };
__global__ void k_prep(WPtrs wp, const float* __restrict__ bf2,
                       const float* __restrict__ x,
                       const int* __restrict__ dst, int E) {
    int i = blockIdx.x * blockDim.x + threadIdx.x;
    if (i < 8 * 8192) {
        int w = i >> 13;
        int r = i & 8191;
        int kp = r >> 7, n = r & 127;
        const float* W = wp.w[w];
        float f0, f1;
        if (w == 7) {
            f0 = (n < NOUT) ? W[(2 * kp) * NOUT + n] : 0.f;
            f1 = (n < NOUT) ? W[(2 * kp + 1) * NOUT + n] : 0.f;
        } else {
            f0 = W[(2 * kp) * 128 + n];
            f1 = W[(2 * kp + 1) * 128 + n];
        }
        uint32_t hi = pack_bf16(f0, f1);
        uint32_t lo = pack_bf16(f0 - blo(hi), f1 - bhi(hi));
        g_whi[w][n * 64 + kp] = hi;
        g_wlo[w][n * 64 + kp] = lo;
    }
    if (i < 128) g_bf2p[i] = (i < NOUT) ? bf2[i] : 0.f;
    if (i < NN * 64) {
        int row = i >> 6, kp = i & 63;
        float2 f = *(const float2*)(x + (size_t)row * D + kp * 2);
        uint32_t hi = pack_bf16(f.x, f.y);
        uint32_t lo = pack_bf16(f.x - blo(hi), f.y - bhi(hi));
        g_xhi[i] = hi;
        g_xlo[i] = lo;
    }
    if (i < E) atomicAdd(&g_cnti[dst[i]], 1);
}

// ---------------- gather mean aggregation on planes (4-edge ILP) ------------
__global__ void k_agg_p(const uint32_t* __restrict__ Ihi, const uint32_t* __restrict__ Ilo,
                        uint32_t* __restrict__ Ohi, uint32_t* __restrict__ Olo) {
    int w = (blockIdx.x * blockDim.x + threadIdx.x) >> 5;
    if (w >= NN) return;
    int lane = threadIdx.x & 31;
    int end = g_rowend[w];
    int start = w ? g_rowend[w - 1] : 0;
    float a0 = 0.f, a1 = 0.f, a2 = 0.f, a3 = 0.f;
    float b0 = 0.f, b1 = 0.f, b2 = 0.f, b3 = 0.f;
    int j = start;
    for (; j + 4 <= end; j += 4) {
        int s0 = g_csrc[j], s1 = g_csrc[j + 1], s2 = g_csrc[j + 2], s3 = g_csrc[j + 3];
        uint2 h0 = *(const uint2*)&Ihi[(size_t)s0 * 64 + lane * 2];
        uint2 l0 = *(const uint2*)&Ilo[(size_t)s0 * 64 + lane * 2];
        uint2 h1 = *(const uint2*)&Ihi[(size_t)s1 * 64 + lane * 2];
        uint2 l1 = *(const uint2*)&Ilo[(size_t)s1 * 64 + lane * 2];
        uint2 h2 = *(const uint2*)&Ihi[(size_t)s2 * 64 + lane * 2];
        uint2 l2 = *(const uint2*)&Ilo[(size_t)s2 * 64 + lane * 2];
        uint2 h3 = *(const uint2*)&Ihi[(size_t)s3 * 64 + lane * 2];
        uint2 l3 = *(const uint2*)&Ilo[(size_t)s3 * 64 + lane * 2];
        a0 += blo(h0.x) + blo(l0.x);  a1 += bhi(h0.x) + bhi(l0.x);
        a2 += blo(h0.y) + blo(l0.y);  a3 += bhi(h0.y) + bhi(l0.y);
        b0 += blo(h1.x) + blo(l1.x);  b1 += bhi(h1.x) + bhi(l1.x);
        b2 += blo(h1.y) + blo(l1.y);  b3 += bhi(h1.y) + bhi(l1.y);
        a0 += blo(h2.x) + blo(l2.x);  a1 += bhi(h2.x) + bhi(l2.x);
        a2 += blo(h2.y) + blo(l2.y);  a3 += bhi(h2.y) + bhi(l2.y);
        b0 += blo(h3.x) + blo(l3.x);  b1 += bhi(h3.x) + bhi(l3.x);
        b2 += blo(h3.y) + blo(l3.y);  b3 += bhi(h3.y) + bhi(l3.y);
    }
    for (; j < end; j++) {
        int s = g_csrc[j];
        uint2 h = *(const uint2*)&Ihi[(size_t)s * 64 + lane * 2];
        uint2 l = *(const uint2*)&Ilo[(size_t)s * 64 + lane * 2];
        a0 += blo(h.x) + blo(l.x);  a1 += bhi(h.x) + bhi(l.x);
        a2 += blo(h.y) + blo(l.y);  a3 += bhi(h.y) + bhi(l.y);
    }
    a0 += b0; a1 += b1; a2 += b2; a3 += b3;
    int deg = end - start;
    float sc = deg > 0 ? 1.0f / (float)deg : 0.f;
    a0 *= sc; a1 *= sc; a2 *= sc; a3 *= sc;
    uint32_t h0 = pack_bf16(a0, a1);
    uint32_t l0 = pack_bf16(a0 - blo(h0), a1 - bhi(h0));
    uint32_t h1 = pack_bf16(a2, a3);
    uint32_t l1 = pack_bf16(a2 - blo(h1), a3 - bhi(h1));
    *(uint2*)&Ohi[(size_t)w * 64 + lane * 2] = make_uint2(h0, h1);
    *(uint2*)&Olo[(size_t)w * 64 + lane * 2] = make_uint2(l0, l1);
}

// ---------------- async double-buffered bf16 3-pass GEMM (ldmatrix, 1 sync/chunk)
#define PST    20
#define PLSZ   2560
#define STSZ   (4 * PLSZ)
#define SMEMB  (2 * STSZ * 4)
// OUTMODE: 0 = planes, 1 = planes + f32
template <bool DUAL, bool RELU, int OUTMODE>
__global__ __launch_bounds__(256, 2) void k_mma_p(
    const uint32_t* __restrict__ ALhi, const uint32_t* __restrict__ ALlo,
    const uint32_t* __restrict__ ARhi, const uint32_t* __restrict__ ARlo,
    const uint32_t* __restrict__ BhiL, const uint32_t* __restrict__ BloL,
    const uint32_t* __restrict__ BhiR, const uint32_t* __restrict__ BloR,
    const float* __restrict__ bias,
    uint32_t* __restrict__ OHi, uint32_t* __restrict__ OLo,
    float* __restrict__ Of32, int nrows)
{
    extern __shared__ uint32_t sm[];
    const uint32_t sb = smem_u32(sm);
    const int tid = threadIdx.x;
    const int wid = tid >> 5, lane = tid & 31;
    const int wr = wid >> 1, wc = wid & 1;
    const int row0 = blockIdx.x * 128;
    const int warp_m = wr * 32;
    const int warp_n = wc * 64;
    const int lq = lane >> 2;
    const int lr = lane & 3;
    const int NCH = DUAL ? 8 : 4;

    const uint32_t aRow = (uint32_t)(warp_m + (lane & 15)) * PST + ((lane & 16) >> 2);
    const uint32_t bRow = (uint32_t)(warp_n + (lane & 7) + ((lane & 16) >> 1)) * PST
                        + ((lane & 8) >> 3) * 4;

    auto issue = [&](int ch) {
        const bool right = DUAL && (ch >= 4);
        const uint32_t* Ah = right ? ARhi : ALhi;
        const uint32_t* Al = right ? ARlo : ALlo;
        const uint32_t* Bh = right ? BhiR : BhiL;
        const uint32_t* Bl = right ? BloR : BloL;
        const int kpb = (ch & 3) * 16;
        const uint32_t base = sb + (uint32_t)(ch & 1) * STSZ * 4;
#pragma unroll
        for (int c = tid; c < 512; c += 256) {
            int r = c >> 2, kg = (c & 3) * 4;
            uint32_t doff = (uint32_t)(r * PST + kg) * 4;
            size_t asrc = (size_t)(row0 + r) * 64 + kpb + kg;
            size_t bsrc = (size_t)r * 64 + kpb + kg;
            cpa16(base + doff,                Ah + asrc);
            cpa16(base + PLSZ * 4 + doff,     Al + asrc);
            cpa16(base + 2 * PLSZ * 4 + doff, Bh + bsrc);
            cpa16(base + 3 * PLSZ * 4 + doff, Bl + bsrc);
        }
        CPA_COMMIT();
    };

    float acc[2][8][4];
#pragma unroll
    for (int m = 0; m < 2; m++)
#pragma unroll
        for (int n = 0; n < 8; n++)
#pragma unroll
            for (int i = 0; i < 4; i++) acc[m][n][i] = 0.f;

    issue(0);
    for (int ch = 0; ch < NCH; ch++) {
        CPA_WAIT0();
        __syncthreads();
        if (ch + 1 < NCH) issue(ch + 1);

        const uint32_t stA = sb + (uint32_t)(ch & 1) * STSZ * 4;

#pragma unroll
        for (int kbu = 0; kbu < 16; kbu += 8) {
            uint32_t ahi[2][4], alo[2][4];
#pragma unroll
            for (int m = 0; m < 2; m++) {
                uint32_t ao = (aRow + (uint32_t)m * 16 * PST + kbu) * 4;
                LDSM4(ahi[m], stA + ao);
                LDSM4(alo[m], stA + PLSZ * 4 + ao);
            }
            uint32_t bh[4][4], bl[4][4];
#pragma unroll
            for (int p = 0; p < 4; p++) {
                uint32_t bo = (bRow + (uint32_t)p * 16 * PST + kbu) * 4;
                LDSM4(bh[p], stA + 2 * PLSZ * 4 + bo);
                LDSM4(bl[p], stA + 3 * PLSZ * 4 + bo);
            }
            // pass-sweep ordering: per-acc sequence (hi·bh, lo·bh, hi·bl) is
            // preserved -> bitwise-identical result, but 15 independent MMAs
            // now sit between successive writes to any given accumulator.
#pragma unroll
            for (int p = 0; p < 4; p++)
#pragma unroll
                for (int m = 0; m < 2; m++) {
                    MMA_BF16(acc[m][2 * p],     ahi[m], bh[p]);
                    MMA_BF16(acc[m][2 * p + 1], ahi[m], (bh[p] + 2));
                }
#pragma unroll
            for (int p = 0; p < 4; p++)
#pragma unroll
                for (int m = 0; m < 2; m++) {
                    MMA_BF16(acc[m][2 * p],     alo[m], bh[p]);
                    MMA_BF16(acc[m][2 * p + 1], alo[m], (bh[p] + 2));
                }
#pragma unroll
            for (int p = 0; p < 4; p++)
#pragma unroll
                for (int m = 0; m < 2; m++) {
                    MMA_BF16(acc[m][2 * p],     ahi[m], bl[p]);
                    MMA_BF16(acc[m][2 * p + 1], ahi[m], (bl[p] + 2));
                }
        }
    }

#pragma unroll
    for (int m = 0; m < 2; m++) {
#pragma unroll
        for (int half = 0; half < 2; half++) {
            int row = row0 + warp_m + m * 16 + lq + half * 8;
            if (row >= nrows) continue;
#pragma unroll
            for (int n = 0; n < 8; n++) {
                int c = warp_n + n * 8 + lr * 2;
                float v0 = acc[m][n][half * 2 + 0] + bias[c];
                float v1 = acc[m][n][half * 2 + 1] + bias[c + 1];
                if (RELU) { v0 = fmaxf(v0, 0.f); v1 = fmaxf(v1, 0.f); }
                uint32_t hi = pack_bf16(v0, v1);
                uint32_t lo = pack_bf16(v0 - blo(hi), v1 - bhi(hi));
                OHi[(size_t)row * 64 + (c >> 1)] = hi;
                OLo[(size_t)row * 64 + (c >> 1)] = lo;
                if (OUTMODE == 1)
                    *(float2*)(Of32 + (size_t)row * D + c) = make_float2(v0, v1);
            }
        }
    }
}

// ---------------- fused fc2 (N=64 padded) + log_softmax (ldmatrix) ---------
#define BST 20
#define FA_PLSZ (128 * PST)
#define FA_ST   (2 * FA_PLSZ)
#define FB_PL   (64 * BST)
#define FB_OFF  (2 * FA_ST)
#define F2SMEM  ((FB_OFF + 8 * FB_PL) * 4)
__global__ __launch_bounds__(256, 2) void k_fc2lsm(
    const uint32_t* __restrict__ Ahi_g, const uint32_t* __restrict__ Alo_g,
    const uint32_t* __restrict__ Bh_g, const uint32_t* __restrict__ Bl_g,
    const float* __restrict__ bias, float* __restrict__ out, int nrows)
{
    extern __shared__ uint32_t sm[];
    const uint32_t sb = smem_u32(sm);
    const int tid = threadIdx.x;
    const int wid = tid >> 5, lane = tid & 31;
    const int row0 = blockIdx.x * 128;
    const int lq = lane >> 2;
    const int lr = lane & 3;

    const uint32_t aRow = (uint32_t)(wid * 16 + (lane & 15)) * PST + ((lane & 16) >> 2);
    const uint32_t bRow = (uint32_t)((lane & 7) + ((lane & 16) >> 1)) * BST
                        + ((lane & 8) >> 3) * 4;

    {
        int c = tid;
        int col = c >> 2, kg = (c & 3) * 4;
#pragma unroll
        for (int ch = 0; ch < 4; ch++) {
            size_t src = (size_t)col * 64 + ch * 16 + kg;
            uint32_t doff = (uint32_t)(col * BST + kg) * 4;
            cpa16(sb + (FB_OFF + (2 * ch) * FB_PL) * 4 + doff,     Bh_g + src);
            cpa16(sb + (FB_OFF + (2 * ch + 1) * FB_PL) * 4 + doff, Bl_g + src);
        }
    }
    CPA_COMMIT();

    auto issueA = [&](int ch) {
        const uint32_t base = sb + (uint32_t)(ch & 1) * FA_ST * 4;
        const int kpb = ch * 16;
#pragma unroll
        for (int c = tid; c < 512; c += 256) {
            int r = c >> 2, kg = (c & 3) * 4;
            uint32_t doff = (uint32_t)(r * PST + kg) * 4;
            size_t src = (size_t)(row0 + r) * 64 + kpb + kg;
            cpa16(base + doff,               Ahi_g + src);
            cpa16(base + FA_PLSZ * 4 + doff, Alo_g + src);
        }
        CPA_COMMIT();
    };

    float acc[8][4];
#pragma unroll
    for (int n = 0; n < 8; n++)
#pragma unroll
        for (int i = 0; i < 4; i++) acc[n][i] = 0.f;

    issueA(0);
    for (int ch = 0; ch < 4; ch++) {
        if (ch + 1 < 4) { issueA(ch + 1); CPA_WAIT1(); }
        else            { CPA_WAIT0(); }
        __syncthreads();

        const uint32_t stA = sb + (uint32_t)(ch & 1) * FA_ST * 4;
        const uint32_t stB = sb + (uint32_t)(FB_OFF + (2 * ch) * FB_PL) * 4;

#pragma unroll
        for (int kbu = 0; kbu < 16; kbu += 8) {
            uint32_t ahi[4], alo[4];
            uint32_t ao = (aRow + kbu) * 4;
            LDSM4(ahi, stA + ao);
            LDSM4(alo, stA + FA_PLSZ * 4 + ao);
            uint32_t bh[4][4], bl[4][4];
#pragma unroll
            for (int p = 0; p < 4; p++) {
                uint32_t bo = (bRow + (uint32_t)p * 16 * BST + kbu) * 4;
                LDSM4(bh[p], stB + bo);
                LDSM4(bl[p], stB + FB_PL * 4 + bo);
            }
            // pass-sweep (bitwise-identical ordering per accumulator)
#pragma unroll
            for (int p = 0; p < 4; p++) {
                MMA_BF16(acc[2 * p],     ahi, bh[p]);
                MMA_BF16(acc[2 * p + 1], ahi, (bh[p] + 2));
            }
#pragma unroll
            for (int p = 0; p < 4; p++) {
                MMA_BF16(acc[2 * p],     alo, bh[p]);
                MMA_BF16(acc[2 * p + 1], alo, (bh[p] + 2));
            }
#pragma unroll
            for (int p = 0; p < 4; p++) {
                MMA_BF16(acc[2 * p],     ahi, bl[p]);
                MMA_BF16(acc[2 * p + 1], ahi, (bl[p] + 2));
            }
        }
        __syncthreads();
    }

#pragma unroll
    for (int half = 0; half < 2; half++) {
        int row = row0 + wid * 16 + lq + half * 8;
        float z[5][2];
        float mx = -1e30f;
#pragma unroll
        for (int n = 0; n < 5; n++) {
            int c = n * 8 + lr * 2;
            z[n][0] = acc[n][half * 2 + 0] + bias[c];
            z[n][1] = acc[n][half * 2 + 1] + bias[c + 1];
            mx = fmaxf(mx, fmaxf(z[n][0], z[n][1]));
        }
        mx = fmaxf(mx, __shfl_xor_sync(0xffffffffu, mx, 1));
        mx = fmaxf(mx, __shfl_xor_sync(0xffffffffu, mx, 2));
        float s = 0.f;
#pragma unroll
        for (int n = 0; n < 5; n++)
            s += expf(z[n][0] - mx) + expf(z[n][1] - mx);
        s += __shfl_xor_sync(0xffffffffu, s, 1);
        s += __shfl_xor_sync(0xffffffffu, s, 2);
        float l = mx + logf(s);
        if (row < nrows) {
#pragma unroll
            for (int n = 0; n < 5; n++) {
                int c = n * 8 + lr * 2;
                *(float2*)(out + (size_t)row * NOUT + c) =
                    make_float2(z[n][0] - l, z[n][1] - l);
            }
        }
    }
}

// ---------------- launch ----------------
extern "C" void kernel_launch(void* const* d_in, const int* in_sizes, int n_in,
                              void* d_out, int out_size) {
    const float* x    = (const float*)d_in[0];
    const int* ei     = (const int*)d_in[1];   // int32 (JAX x64-disabled)
    const int E = in_sizes[1] / 2;
    const int* src = ei;
    const int* dst = ei + E;
    const float* W1l = (const float*)d_in[2];
    const float* b1  = (const float*)d_in[3];
    const float* W1r = (const float*)d_in[4];
    const float* W2l = (const float*)d_in[5];
    const float* b2  = (const float*)d_in[6];
    const float* W2r = (const float*)d_in[7];
    const float* W3l = (const float*)d_in[8];
    const float* b3  = (const float*)d_in[9];
    const float* W3r = (const float*)d_in[10];
    const float* Wf1 = (const float*)d_in[11];
    const float* bf1 = (const float*)d_in[12];
    const float* Wf2 = (const float*)d_in[13];
    const float* bf2 = (const float*)d_in[14];

    float* out = (float*)d_out;

    uint32_t *xhi, *xlo, *ahi, *alo, *p1hi, *p1lo, *p2hi, *p2lo, *whi, *wlo;
    float *hC, *bf2p;
    cudaGetSymbolAddress((void**)&xhi, g_xhi);
    cudaGetSymbolAddress((void**)&xlo, g_xlo);
    cudaGetSymbolAddress((void**)&ahi, g_ahi);
    cudaGetSymbolAddress((void**)&alo, g_alo);
    cudaGetSymbolAddress((void**)&p1hi, g_p1hi);
    cudaGetSymbolAddress((void**)&p1lo, g_p1lo);
    cudaGetSymbolAddress((void**)&p2hi, g_p2hi);
    cudaGetSymbolAddress((void**)&p2lo, g_p2lo);
    cudaGetSymbolAddress((void**)&whi, g_whi);
    cudaGetSymbolAddress((void**)&wlo, g_wlo);
    cudaGetSymbolAddress((void**)&hC, g_hC);
    cudaGetSymbolAddress((void**)&bf2p, g_bf2p);

    float* h_out = (out_size >= NN * (NOUT + D)) ? (out + (size_t)NN * NOUT) : hC;

    cudaFuncSetAttribute(k_mma_p<true, true, 0>,  cudaFuncAttributeMaxDynamicSharedMemorySize, SMEMB);
    cudaFuncSetAttribute(k_mma_p<true, false, 1>, cudaFuncAttributeMaxDynamicSharedMemorySize, SMEMB);
    cudaFuncSetAttribute(k_mma_p<false, true, 0>, cudaFuncAttributeMaxDynamicSharedMemorySize, SMEMB);
    cudaFuncSetAttribute(k_fc2lsm, cudaFuncAttributeMaxDynamicSharedMemorySize, F2SMEM);

    const int T = 256;
    const int gE    = (E + T - 1) / T;
    const int gAggW = (int)(((size_t)NN * 32 + T - 1) / T);
    const int gGemm = (NN + 127) / 128;

    WPtrs wp;
    wp.w[0] = W1l; wp.w[1] = W1r; wp.w[2] = W2l; wp.w[3] = W2r;
    wp.w[4] = W3l; wp.w[5] = W3r; wp.w[6] = Wf1; wp.w[7] = Wf2;

#define WH(i) (whi + (size_t)(i) * 8192)
#define WL(i) (wlo + (size_t)(i) * 8192)

    k_prep<<<(NN * 64 + T - 1) / T, T>>>(wp, bf2, x, dst, E);
    k_scan1<<<NB, SCAN_B>>>(NN);
    k_scan3<<<NB, SCAN_B>>>(NN);
    k_fill<<<gE, T>>>(src, dst, E);

    // layer 1
    k_agg_p<<<gAggW, T>>>(xhi, xlo, ahi, alo);
    k_mma_p<true, true, 0><<<gGemm, T, SMEMB>>>(ahi, alo, xhi, xlo,
        WH(0), WL(0), WH(1), WL(1), b1, p1hi, p1lo, nullptr, NN);
    // layer 2
    k_agg_p<<<gAggW, T>>>(p1hi, p1lo, ahi, alo);
    k_mma_p<true, true, 0><<<gGemm, T, SMEMB>>>(ahi, alo, p1hi, p1lo,
        WH(2), WL(2), WH(3), WL(3), b2, p2hi, p2lo, nullptr, NN);
    // layer 3 (no relu): planes + exact f32 h
    k_agg_p<<<gAggW, T>>>(p2hi, p2lo, ahi, alo);
    k_mma_p<true, false, 1><<<gGemm, T, SMEMB>>>(ahi, alo, p2hi, p2lo,
        WH(4), WL(4), WH(5), WL(5), b3, p1hi, p1lo, h_out, NN);
    // fc1 (relu) -> p2 planes
    k_mma_p<false, true, 0><<<gGemm, T, SMEMB>>>(p1hi, p1lo, nullptr, nullptr,
        WH(6), WL(6), nullptr, nullptr, bf1, p2hi, p2lo, nullptr, NN);
    // fc2 + log_softmax fused
    k_fc2lsm<<<gGemm, T, F2SMEM>>>(p2hi, p2lo, WH(7), WL(7), bf2p, out, NN);
}